// round 6
// baseline (speedup 1.0000x reference)
#include <cuda_runtime.h>
#include <cuda_bf16.h>
#include <cuda_fp16.h>
#include <math.h>

#define NN 50000
#define NE 800000

// ---------------- device scratch ----------------
__device__ float  g_xl1[NN * 128];
__device__ __half g_xr1h[NN * 128];
__device__ float  g_h1 [NN * 128];
__device__ float  g_xl2[NN * 64];
__device__ float  g_xr2[NN * 64];
__device__ int    g_cnt[NN];
__device__ int    g_rowptr[NN + 1];
__device__ int    g_blocksum[64];
__device__ int2   g_edge[NE];        // {src, bitcast(edge_attr)}

// ---------------- CSR build ----------------
__global__ void k_zero() {
    int i = blockIdx.x * blockDim.x + threadIdx.x;
    for (; i < NN; i += gridDim.x * blockDim.x) g_cnt[i] = 0;
}

__global__ void k_hist(const int* __restrict__ ei) {
    int e = blockIdx.x * blockDim.x + threadIdx.x;
    if (e < NE) {
        unsigned dst = (unsigned)ei[NE + e];
        if (dst < NN) atomicAdd(&g_cnt[dst], 1);
    }
}

__global__ void k_scan1() {
    __shared__ int sh[1024];
    int i = blockIdx.x * 1024 + threadIdx.x;
    int v = (i < NN) ? g_cnt[i] : 0;
    sh[threadIdx.x] = v;
    __syncthreads();
    for (int off = 1; off < 1024; off <<= 1) {
        int t = (threadIdx.x >= off) ? sh[threadIdx.x - off] : 0;
        __syncthreads();
        sh[threadIdx.x] += t;
        __syncthreads();
    }
    int incl = sh[threadIdx.x];
    if (i < NN) g_rowptr[i] = incl - v;
    if (threadIdx.x == 1023) g_blocksum[blockIdx.x] = incl;
}

__global__ void k_scan2(int nblk) {
    __shared__ int sh[64];
    int t = threadIdx.x;
    int v = (t < nblk) ? g_blocksum[t] : 0;
    sh[t] = v;
    __syncthreads();
    for (int off = 1; off < 64; off <<= 1) {
        int u = (t >= off) ? sh[t - off] : 0;
        __syncthreads();
        sh[t] += u;
        __syncthreads();
    }
    if (t < nblk) g_blocksum[t] = sh[t] - v;   // exclusive
}

__global__ void k_scan3() {
    int i = blockIdx.x * blockDim.x + threadIdx.x;
    if (i < NN) {
        int r = g_rowptr[i] + g_blocksum[i >> 10];
        g_rowptr[i] = r;
        g_cnt[i] = r;
    }
    if (i == 0) g_rowptr[NN] = NE;
}

__global__ void k_scatter(const int* __restrict__ ei,
                          const float* __restrict__ edge_attr) {
    int e = blockIdx.x * blockDim.x + threadIdx.x;
    if (e < NE) {
        unsigned dst = (unsigned)ei[NE + e];
        unsigned src = (unsigned)ei[e];
        if (dst < NN && src < NN) {
            int pos = atomicAdd(&g_cnt[dst], 1);
            g_edge[pos] = make_int2((int)src, __float_as_int(edge_attr[e]));
        }
    }
}

// ---------------- Layer 1 projections: x[N,10] @ W[10,128] ----------------
__global__ __launch_bounds__(128) void k_proj1(const float* __restrict__ x,
                                               const float* __restrict__ Wl,
                                               const float* __restrict__ Wr) {
    __shared__ float swl[10 * 128];
    __shared__ float swr[10 * 128];
    int c = threadIdx.x;
    for (int k = c; k < 10 * 128; k += 128) { swl[k] = Wl[k]; swr[k] = Wr[k]; }
    __syncthreads();
    int n0 = blockIdx.x * 8;
#pragma unroll
    for (int t = 0; t < 8; t++) {
        int n = n0 + t;
        if (n >= NN) break;
        float al = 0.f, ar = 0.f;
#pragma unroll
        for (int k = 0; k < 10; k++) {
            float xv = x[n * 10 + k];
            al = fmaf(xv, swl[k * 128 + c], al);
            ar = fmaf(xv, swr[k * 128 + c], ar);
        }
        g_xl1[n * 128 + c]  = al;
        g_xr1h[n * 128 + c] = __float2half_rn(ar);
    }
}

// ---------------- Layer 1 agg: head = lane>>3, lane owns 4 consecutive channels ----------
__global__ __launch_bounds__(256) void k_agg1(const float* __restrict__ att1,
                                              const float* __restrict__ W1e,
                                              const float* __restrict__ b1,
                                              const float* __restrict__ g1,
                                              const float* __restrict__ be1) {
    int warp = threadIdx.x >> 5, lane = threadIdx.x & 31;
    int node = blockIdx.x * 8 + warp;
    if (node >= NN) return;

    int cb = (lane >> 3) * 32 + (lane & 7) * 4;   // base channel (x4)

    float4 att = *(const float4*)(att1 + cb);
    float4 we  = *(const float4*)(W1e  + cb);
    float4 xli = *(const float4*)(g_xl1 + node * 128 + cb);
    float4 acc = make_float4(0.f, 0.f, 0.f, 0.f);
    float  den = 0.f;

    int p0 = g_rowptr[node], p1 = g_rowptr[node + 1];
    int p = p0;
    for (; p + 3 < p1; p += 4) {
        float4 xr[4]; float lg[4];
#pragma unroll
        for (int j = 0; j < 4; j++) {
            int2 eg = g_edge[p + j];
            float eav = __int_as_float(eg.y);
            uint2 u = *(const uint2*)&g_xr1h[eg.x * 128 + cb];
            float2 fa = __half22float2(*(__half2*)&u.x);
            float2 fb = __half22float2(*(__half2*)&u.y);
            xr[j] = make_float4(fa.x, fa.y, fb.x, fb.y);
            float t, l;
            t = fmaf(eav, we.x, xli.x + xr[j].x); t = fmaxf(t, 0.2f * t); l = t * att.x;
            t = fmaf(eav, we.y, xli.y + xr[j].y); t = fmaxf(t, 0.2f * t); l = fmaf(t, att.y, l);
            t = fmaf(eav, we.z, xli.z + xr[j].z); t = fmaxf(t, 0.2f * t); l = fmaf(t, att.z, l);
            t = fmaf(eav, we.w, xli.w + xr[j].w); t = fmaxf(t, 0.2f * t); l = fmaf(t, att.w, l);
            lg[j] = l;
        }
#pragma unroll
        for (int off = 4; off; off >>= 1) {
#pragma unroll
            for (int j = 0; j < 4; j++)
                lg[j] += __shfl_xor_sync(0xffffffffu, lg[j], off);
        }
#pragma unroll
        for (int j = 0; j < 4; j++) {
            float w = __expf(lg[j]);
            den += w;
            acc.x = fmaf(w, xr[j].x, acc.x);
            acc.y = fmaf(w, xr[j].y, acc.y);
            acc.z = fmaf(w, xr[j].z, acc.z);
            acc.w = fmaf(w, xr[j].w, acc.w);
        }
    }
    for (; p < p1; p++) {
        int2 eg = g_edge[p];
        float eav = __int_as_float(eg.y);
        uint2 u = *(const uint2*)&g_xr1h[eg.x * 128 + cb];
        float2 fa = __half22float2(*(__half2*)&u.x);
        float2 fb = __half22float2(*(__half2*)&u.y);
        float t, l;
        t = fmaf(eav, we.x, xli.x + fa.x); t = fmaxf(t, 0.2f * t); l = t * att.x;
        t = fmaf(eav, we.y, xli.y + fa.y); t = fmaxf(t, 0.2f * t); l = fmaf(t, att.y, l);
        t = fmaf(eav, we.z, xli.z + fb.x); t = fmaxf(t, 0.2f * t); l = fmaf(t, att.z, l);
        t = fmaf(eav, we.w, xli.w + fb.y); t = fmaxf(t, 0.2f * t); l = fmaf(t, att.w, l);
#pragma unroll
        for (int off = 4; off; off >>= 1)
            l += __shfl_xor_sync(0xffffffffu, l, off);
        float w = __expf(l);
        den += w;
        acc.x = fmaf(w, fa.x, acc.x);
        acc.y = fmaf(w, fa.y, acc.y);
        acc.z = fmaf(w, fb.x, acc.z);
        acc.w = fmaf(w, fb.y, acc.w);
    }

    float inv = (den > 0.f) ? (1.f / den) : 0.f;
    float4 bb = *(const float4*)(b1 + cb);
    float o0 = acc.x * inv + bb.x;
    float o1 = acc.y * inv + bb.y;
    float o2 = acc.z * inv + bb.z;
    float o3 = acc.w * inv + bb.w;

    float s = o0 + o1 + o2 + o3;
#pragma unroll
    for (int off = 16; off; off >>= 1) s += __shfl_xor_sync(0xffffffffu, s, off);
    float mu = s * (1.f / 128.f);
    float d0 = o0 - mu, d1 = o1 - mu, d2 = o2 - mu, d3 = o3 - mu;
    float vs = fmaf(d0, d0, fmaf(d1, d1, fmaf(d2, d2, d3 * d3)));
#pragma unroll
    for (int off = 16; off; off >>= 1) vs += __shfl_xor_sync(0xffffffffu, vs, off);
    float rstd = rsqrtf(vs * (1.f / 128.f) + 1e-5f);

    float4 gg = *(const float4*)(g1  + cb);
    float4 be = *(const float4*)(be1 + cb);
    float y0 = d0 * rstd * gg.x + be.x; y0 = (y0 > 0.f) ? y0 : expm1f(y0);
    float y1 = d1 * rstd * gg.y + be.y; y1 = (y1 > 0.f) ? y1 : expm1f(y1);
    float y2 = d2 * rstd * gg.z + be.z; y2 = (y2 > 0.f) ? y2 : expm1f(y2);
    float y3 = d3 * rstd * gg.w + be.w; y3 = (y3 > 0.f) ? y3 : expm1f(y3);
    *(float4*)(g_h1 + node * 128 + cb) = make_float4(y0, y1, y2, y3);
}

// ---------------- Layer 2 dual projection: h1[N,128] @ {W2l,W2r}[128,64] ----------------
__global__ __launch_bounds__(256) void k_proj2(const float* __restrict__ Wl,
                                               const float* __restrict__ Wr) {
    __shared__ float shh[32 * 128];
    __shared__ float swl[64 * 64];
    __shared__ float swr[64 * 64];
    int tid = threadIdx.x;
    int oc = tid & 63, part = tid >> 6;
    int n0 = blockIdx.x * 32;
    for (int idx = tid; idx < 32 * 128; idx += 256) {
        int n = n0 + (idx >> 7);
        shh[idx] = (n < NN) ? g_h1[n * 128 + (idx & 127)] : 0.f;
    }

    float accl[8], accr[8];
#pragma unroll
    for (int i = 0; i < 8; i++) { accl[i] = 0.f; accr[i] = 0.f; }

#pragma unroll
    for (int half = 0; half < 2; half++) {
        __syncthreads();
        for (int idx = tid; idx < 64 * 64; idx += 256) {
            swl[idx] = Wl[half * 4096 + idx];
            swr[idx] = Wr[half * 4096 + idx];
        }
        __syncthreads();
        int kb = half * 64;
#pragma unroll 4
        for (int k = 0; k < 64; k += 4) {
            float l0 = swl[(k + 0) * 64 + oc], r0 = swr[(k + 0) * 64 + oc];
            float l1 = swl[(k + 1) * 64 + oc], r1 = swr[(k + 1) * 64 + oc];
            float l2 = swl[(k + 2) * 64 + oc], r2 = swr[(k + 2) * 64 + oc];
            float l3 = swl[(k + 3) * 64 + oc], r3 = swr[(k + 3) * 64 + oc];
#pragma unroll
            for (int i = 0; i < 8; i++) {
                int nn = part + i * 4;
                float4 h4 = *(const float4*)&shh[nn * 128 + kb + k];
                accl[i] = fmaf(h4.x, l0, fmaf(h4.y, l1, fmaf(h4.z, l2, fmaf(h4.w, l3, accl[i]))));
                accr[i] = fmaf(h4.x, r0, fmaf(h4.y, r1, fmaf(h4.z, r2, fmaf(h4.w, r3, accr[i]))));
            }
        }
    }
#pragma unroll
    for (int i = 0; i < 8; i++) {
        int n = n0 + part + i * 4;
        if (n < NN) {
            g_xl2[n * 64 + oc] = accl[i];
            g_xr2[n * 64 + oc] = accr[i];
        }
    }
}

// ---------------- Layer 2 agg: lane owns channels {2*lane, 2*lane+1} (fp32) ----------
__global__ __launch_bounds__(256) void k_agg2(const float* __restrict__ att2,
                                              const float* __restrict__ W2e,
                                              const float* __restrict__ b2,
                                              const float* __restrict__ g2,
                                              const float* __restrict__ be2,
                                              float* __restrict__ out) {
    int warp = threadIdx.x >> 5, lane = threadIdx.x & 31;
    int node = blockIdx.x * 8 + warp;
    if (node >= NN) return;

    int cb = lane * 2;
    float2 att = *(const float2*)(att2 + cb);
    float2 we  = *(const float2*)(W2e  + cb);
    float2 xli = *(const float2*)(g_xl2 + node * 64 + cb);
    float acc0 = 0.f, acc1 = 0.f, den = 0.f;
    const float2* xr_base = (const float2*)g_xr2;

    int p0 = g_rowptr[node], p1 = g_rowptr[node + 1];
    int p = p0;
    for (; p + 3 < p1; p += 4) {
        float2 xr[4]; float lg[4];
#pragma unroll
        for (int j = 0; j < 4; j++) {
            int2 eg = g_edge[p + j];
            float eav = __int_as_float(eg.y);
            xr[j] = xr_base[eg.x * 32 + lane];
            float t, l;
            t = fmaf(eav, we.x, xli.x + xr[j].x); t = fmaxf(t, 0.2f * t); l = t * att.x;
            t = fmaf(eav, we.y, xli.y + xr[j].y); t = fmaxf(t, 0.2f * t); l = fmaf(t, att.y, l);
            lg[j] = l;
        }
#pragma unroll
        for (int off = 16; off; off >>= 1) {
#pragma unroll
            for (int j = 0; j < 4; j++)
                lg[j] += __shfl_xor_sync(0xffffffffu, lg[j], off);
        }
#pragma unroll
        for (int j = 0; j < 4; j++) {
            float w = __expf(lg[j]);
            den += w;
            acc0 = fmaf(w, xr[j].x, acc0);
            acc1 = fmaf(w, xr[j].y, acc1);
        }
    }
    for (; p < p1; p++) {
        int2 eg = g_edge[p];
        float eav = __int_as_float(eg.y);
        float2 xr0 = xr_base[eg.x * 32 + lane];
        float t, l;
        t = fmaf(eav, we.x, xli.x + xr0.x); t = fmaxf(t, 0.2f * t); l = t * att.x;
        t = fmaf(eav, we.y, xli.y + xr0.y); t = fmaxf(t, 0.2f * t); l = fmaf(t, att.y, l);
#pragma unroll
        for (int off = 16; off; off >>= 1)
            l += __shfl_xor_sync(0xffffffffu, l, off);
        float w = __expf(l);
        den += w;
        acc0 = fmaf(w, xr0.x, acc0);
        acc1 = fmaf(w, xr0.y, acc1);
    }

    float inv = (den > 0.f) ? (1.f / den) : 0.f;
    float2 bb = *(const float2*)(b2 + cb);
    float o0 = acc0 * inv + bb.x;
    float o1 = acc1 * inv + bb.y;

    float s = o0 + o1;
#pragma unroll
    for (int off = 16; off; off >>= 1) s += __shfl_xor_sync(0xffffffffu, s, off);
    float mu = s * (1.f / 64.f);
    float d0 = o0 - mu, d1 = o1 - mu;
    float vs = fmaf(d0, d0, d1 * d1);
#pragma unroll
    for (int off = 16; off; off >>= 1) vs += __shfl_xor_sync(0xffffffffu, vs, off);
    float rstd = rsqrtf(vs * (1.f / 64.f) + 1e-5f);

    float2 gg = *(const float2*)(g2  + cb);
    float2 be = *(const float2*)(be2 + cb);
    float y0 = d0 * rstd * gg.x + be.x; y0 = (y0 > 0.f) ? y0 : expm1f(y0);
    float y1 = d1 * rstd * gg.y + be.y; y1 = (y1 > 0.f) ? y1 : expm1f(y1);
    *(float2*)(out + node * 64 + cb) = make_float2(y0, y1);
}

// ---------------- launcher ----------------
extern "C" void kernel_launch(void* const* d_in, const int* in_sizes, int n_in,
                              void* d_out, int out_size) {
    const float* x    = (const float*)d_in[0];
    const float* ea   = (const float*)d_in[1];
    const float* W1l  = (const float*)d_in[2];
    const float* W1r  = (const float*)d_in[3];
    const float* W1e  = (const float*)d_in[4];
    const float* att1 = (const float*)d_in[5];
    const float* b1   = (const float*)d_in[6];
    const float* ln1g = (const float*)d_in[7];
    const float* ln1b = (const float*)d_in[8];
    const float* W2l  = (const float*)d_in[9];
    const float* W2r  = (const float*)d_in[10];
    const float* W2e  = (const float*)d_in[11];
    const float* att2 = (const float*)d_in[12];
    const float* b2   = (const float*)d_in[13];
    const float* ln2g = (const float*)d_in[14];
    const float* ln2b = (const float*)d_in[15];
    const int*   ei   = (const int*)d_in[16];   // int32 [2, NE]
    float* out = (float*)d_out;

    const int NBLK_SCAN = (NN + 1023) / 1024;   // 49

    k_zero<<<200, 256>>>();
    k_hist<<<(NE + 255) / 256, 256>>>(ei);
    k_scan1<<<NBLK_SCAN, 1024>>>();
    k_scan2<<<1, 64>>>(NBLK_SCAN);
    k_scan3<<<(NN + 255) / 256, 256>>>();
    k_scatter<<<(NE + 255) / 256, 256>>>(ei, ea);

    k_proj1<<<(NN + 7) / 8, 128>>>(x, W1l, W1r);
    k_agg1<<<(NN + 7) / 8, 256>>>(att1, W1e, b1, ln1g, ln1b);

    k_proj2<<<(NN + 31) / 32, 256>>>(W2l, W2r);
    k_agg2<<<(NN + 7) / 8, 256>>>(att2, W2e, b2, ln2g, ln2b, out);
}